// round 3
// baseline (speedup 1.0000x reference)
#include <cuda_runtime.h>

#define N_NODES 100000
#define N_EDGES 1600000
#define D_IN    128
#define D_HID   48
#define D_OUT   32

// ---- scratch (device globals: no allocation allowed) ----
__device__ __align__(16) float g_deg [N_NODES];
__device__ __align__(16) float g_dinv[N_NODES];
__device__ __align__(16) float g_norm[N_EDGES];
__device__ __align__(16) float g_h1  [N_NODES * D_HID];
__device__ __align__(16) float g_agg1[N_NODES * D_HID];
__device__ __align__(16) float g_h2  [N_NODES * D_OUT];
__device__ __align__(16) float g_agg2[N_NODES * D_OUT];
__device__ int g_is64;

// ---- dtype detection: int64 edge_index has zero high words ----
__global__ void detect_kernel(const int* __restrict__ ei32) {
    __shared__ int acc;
    if (threadIdx.x == 0) acc = 0;
    __syncthreads();
    int v = 0;
    for (int i = threadIdx.x; i < 2048; i += 256) v |= ei32[2 * i + 1];
    atomicOr(&acc, v);
    __syncthreads();
    if (threadIdx.x == 0) g_is64 = (acc == 0) ? 1 : 0;
}

__device__ __forceinline__ int edge_src(const int* ei, int e) {
    return g_is64 ? ei[2 * e] : ei[e];
}
__device__ __forceinline__ int edge_dst(const int* ei, int e) {
    return g_is64 ? ei[2 * (N_EDGES + e)] : ei[N_EDGES + e];
}

// ---- zero ----
__global__ void zero_kernel(float4* __restrict__ p, int n4) {
    int i = blockIdx.x * blockDim.x + threadIdx.x;
    if (i < n4) p[i] = make_float4(0.f, 0.f, 0.f, 0.f);
}

// ---- degree: deg[dst] += ew ----
__global__ void deg_kernel(const int* __restrict__ ei,
                           const float* __restrict__ ew) {
    int e = blockIdx.x * blockDim.x + threadIdx.x;
    if (e >= N_EDGES) return;
    unsigned d = (unsigned)edge_dst(ei, e);
    if (d < N_NODES) atomicAdd(&g_deg[d], ew[e]);
}

// ---- dinv = rsqrt(deg + 1) ----
__global__ void dinv_kernel() {
    int i = blockIdx.x * blockDim.x + threadIdx.x;
    if (i < N_NODES) g_dinv[i] = rsqrtf(g_deg[i] + 1.0f);
}

// ---- norm[e] = dinv[src]*ew*dinv[dst] ----
__global__ void norm_kernel(const int* __restrict__ ei,
                            const float* __restrict__ ew) {
    int e = blockIdx.x * blockDim.x + threadIdx.x;
    if (e >= N_EDGES) return;
    unsigned s = (unsigned)edge_src(ei, e);
    unsigned d = (unsigned)edge_dst(ei, e);
    float nm = 0.f;
    if (s < N_NODES && d < N_NODES) nm = g_dinv[s] * ew[e] * g_dinv[d];
    g_norm[e] = nm;
}

// ---- GEMM: H[N,M] = X[N,K] @ W[K,M] ----
template <int K, int M, int CK>
__global__ __launch_bounds__(256)
void gemm_kernel(const float* __restrict__ X, const float* __restrict__ W,
                 float* __restrict__ H) {
    __shared__ float Ws[K * M];
    __shared__ float Xs[256 * (CK + 1)];

    const int tid = threadIdx.x;
    for (int i = tid; i < K * M; i += 256) Ws[i] = W[i];

    const int row = blockIdx.x * 256 + tid;
    float acc[M];
#pragma unroll
    for (int j = 0; j < M; j++) acc[j] = 0.f;

    const int F4 = CK / 4;
    for (int kc = 0; kc < K; kc += CK) {
        __syncthreads();
        for (int idx = tid; idx < 256 * F4; idx += 256) {
            int r  = idx / F4;
            int c4 = idx % F4;
            int grow = blockIdx.x * 256 + r;
            float4 v = make_float4(0.f, 0.f, 0.f, 0.f);
            if (grow < N_NODES)
                v = *(const float4*)&X[(size_t)grow * K + kc + c4 * 4];
            float* xp = &Xs[r * (CK + 1) + c4 * 4];
            xp[0] = v.x; xp[1] = v.y; xp[2] = v.z; xp[3] = v.w;
        }
        __syncthreads();
#pragma unroll
        for (int k = 0; k < CK; k++) {
            float xv = Xs[tid * (CK + 1) + k];
#pragma unroll
            for (int j4 = 0; j4 < M / 4; j4++) {
                float4 w = *(const float4*)&Ws[(kc + k) * M + j4 * 4];
                acc[j4 * 4 + 0] += xv * w.x;
                acc[j4 * 4 + 1] += xv * w.y;
                acc[j4 * 4 + 2] += xv * w.z;
                acc[j4 * 4 + 3] += xv * w.w;
            }
        }
    }

    if (row < N_NODES) {
#pragma unroll
        for (int j4 = 0; j4 < M / 4; j4++) {
            float4 o = make_float4(acc[j4 * 4 + 0], acc[j4 * 4 + 1],
                                   acc[j4 * 4 + 2], acc[j4 * 4 + 3]);
            *(float4*)&H[(size_t)row * M + j4 * 4] = o;
        }
    }
}

// ---- scatter: agg[dst] += norm[e] * h[src] ----
template <int M>
__global__ __launch_bounds__(256)
void scatter_kernel(const int* __restrict__ ei,
                    const float* __restrict__ nrm,
                    const float* __restrict__ h,
                    float* __restrict__ agg) {
    const int C = M / 4;
    int t = blockIdx.x * blockDim.x + threadIdx.x;
    if (t >= N_EDGES * C) return;
    int e = t / C;
    int c = t % C;
    unsigned s = (unsigned)edge_src(ei, e);
    unsigned d = (unsigned)edge_dst(ei, e);
    if (s >= N_NODES || d >= N_NODES) return;
    float nm = nrm[e];
    float4 v = *(const float4*)&h[(size_t)s * M + c * 4];
    float* p = &agg[(size_t)d * M + c * 4];
    atomicAdd(p + 0, v.x * nm);
    atomicAdd(p + 1, v.y * nm);
    atomicAdd(p + 2, v.z * nm);
    atomicAdd(p + 3, v.w * nm);
}

// ---- finalize: out = agg + dinv^2 * h + b (optional relu) ----
template <int M, bool RELU>
__global__ void fin_kernel(const float* __restrict__ agg,
                           const float* __restrict__ h,
                           const float* __restrict__ b,
                           float* __restrict__ out) {
    const int C = M / 4;
    int t = blockIdx.x * blockDim.x + threadIdx.x;
    if (t >= N_NODES * C) return;
    int i = t / C;
    int c = t % C;
    float di = g_dinv[i];
    float d2 = di * di;
    float4 a  = *(const float4*)&agg[(size_t)t * 4];
    float4 hv = *(const float4*)&h[(size_t)t * 4];
    float4 bv = *(const float4*)&b[c * 4];
    float4 o;
    o.x = fmaf(d2, hv.x, a.x) + bv.x;
    o.y = fmaf(d2, hv.y, a.y) + bv.y;
    o.z = fmaf(d2, hv.z, a.z) + bv.z;
    o.w = fmaf(d2, hv.w, a.w) + bv.w;
    if (RELU) {
        o.x = fmaxf(o.x, 0.f); o.y = fmaxf(o.y, 0.f);
        o.z = fmaxf(o.z, 0.f); o.w = fmaxf(o.w, 0.f);
    }
    *(float4*)&out[(size_t)t * 4] = o;
}

extern "C" void kernel_launch(void* const* d_in, const int* in_sizes, int n_in,
                              void* d_out, int out_size) {
    const float* x  = (const float*)d_in[0];
    const int*   ei = (const int*)d_in[1];
    const float* ew = (const float*)d_in[2];
    const float* W1 = (const float*)d_in[3];
    const float* b1 = (const float*)d_in[4];
    const float* W2 = (const float*)d_in[5];
    const float* b2 = (const float*)d_in[6];
    float* out = (float*)d_out;

    float *deg, *nrm, *h1, *agg1, *h2, *agg2;
    cudaGetSymbolAddress((void**)&deg,  g_deg);
    cudaGetSymbolAddress((void**)&nrm,  g_norm);
    cudaGetSymbolAddress((void**)&h1,   g_h1);
    cudaGetSymbolAddress((void**)&agg1, g_agg1);
    cudaGetSymbolAddress((void**)&h2,   g_h2);
    cudaGetSymbolAddress((void**)&agg2, g_agg2);

    const int T = 256;

    detect_kernel<<<1, 256>>>(ei);

    // zero deg + aggregation buffers
    zero_kernel<<<(N_NODES / 4 + T - 1) / T, T>>>((float4*)deg,  N_NODES / 4);
    zero_kernel<<<(N_NODES * D_HID / 4 + T - 1) / T, T>>>((float4*)agg1, N_NODES * D_HID / 4);
    zero_kernel<<<(N_NODES * D_OUT / 4 + T - 1) / T, T>>>((float4*)agg2, N_NODES * D_OUT / 4);

    // degree + dinv + per-edge norm
    deg_kernel<<<(N_EDGES + T - 1) / T, T>>>(ei, ew);
    dinv_kernel<<<(N_NODES + T - 1) / T, T>>>();
    norm_kernel<<<(N_EDGES + T - 1) / T, T>>>(ei, ew);

    // layer 1
    gemm_kernel<D_IN, D_HID, 16><<<(N_NODES + 255) / 256, 256>>>(x, W1, h1);
    {
        int work = N_EDGES * (D_HID / 4);
        scatter_kernel<D_HID><<<(work + T - 1) / T, T>>>(ei, nrm, h1, agg1);
    }
    {
        int work = N_NODES * (D_HID / 4);
        fin_kernel<D_HID, true><<<(work + T - 1) / T, T>>>(agg1, h1, b1, h1);
    }

    // layer 2
    gemm_kernel<D_HID, D_OUT, 16><<<(N_NODES + 255) / 256, 256>>>(h1, W2, h2);
    {
        int work = N_EDGES * (D_OUT / 4);
        scatter_kernel<D_OUT><<<(work + T - 1) / T, T>>>(ei, nrm, h2, agg2);
    }
    {
        int work = N_NODES * (D_OUT / 4);
        fin_kernel<D_OUT, false><<<(work + T - 1) / T, T>>>(agg2, h2, b2, out);
    }
}

// round 4
// speedup vs baseline: 1.4138x; 1.4138x over previous
#include <cuda_runtime.h>

#define N_NODES 100000
#define N_EDGES 1600000
#define D_IN    128
#define D_HID   48
#define D_OUT   32

typedef unsigned long long ull;

// ---- scratch (device globals: no allocation allowed) ----
__device__ __align__(16) float g_dinv[N_NODES];
__device__ __align__(16) int   g_cnt [N_NODES];
__device__ __align__(16) int   g_rowptr[N_NODES + 1];
__device__ __align__(16) int   g_pos [N_NODES];
__device__ __align__(16) int2  g_rec [N_EDGES];        // {src, ew bits} sorted by dst
__device__ __align__(16) float g_h1  [N_NODES * D_HID];
__device__ __align__(16) float g_ag1 [N_NODES * D_HID];
__device__ __align__(16) float g_h2  [N_NODES * D_OUT];
__device__ int g_is64;

__device__ __forceinline__ int edge_src(const int* ei, int e) {
    return g_is64 ? ei[2 * e] : ei[e];
}
__device__ __forceinline__ int edge_dst(const int* ei, int e) {
    return g_is64 ? ei[2 * (N_EDGES + e)] : ei[N_EDGES + e];
}

// ---- packed f32x2 FMA (full-rate path; ptxas won't emit FFMA2 from C++) ----
__device__ __forceinline__ ull fma2(ull a, ull b, ull c) {
    ull d;
    asm("fma.rn.f32x2 %0, %1, %2, %3;" : "=l"(d) : "l"(a), "l"(b), "l"(c));
    return d;
}
__device__ __forceinline__ ull pack2(float lo, float hi) {
    ull d;
    asm("mov.b64 %0, {%1, %2};" : "=l"(d) : "r"(__float_as_uint(lo)), "r"(__float_as_uint(hi)));
    return d;
}
__device__ __forceinline__ float2 unpack2(ull v) {
    unsigned lo, hi;
    asm("mov.b64 {%0, %1}, %2;" : "=r"(lo), "=r"(hi) : "l"(v));
    return make_float2(__uint_as_float(lo), __uint_as_float(hi));
}

// ---- launch 0: detect edge dtype + zero counts (single block) ----
__global__ void detect_zero_kernel(const int* __restrict__ ei32) {
    for (int i = threadIdx.x; i < N_NODES; i += 256) g_cnt[i] = 0;
    __shared__ int acc;
    if (threadIdx.x == 0) acc = 0;
    __syncthreads();
    int v = 0;
    for (int i = threadIdx.x; i < 2048; i += 256) v |= ei32[2 * i + 1];
    atomicOr(&acc, v);
    __syncthreads();
    if (threadIdx.x == 0) g_is64 = (acc == 0) ? 1 : 0;
}

// ---- launch 1: in-degree counts ----
__global__ void count_kernel(const int* __restrict__ ei) {
    int e = blockIdx.x * blockDim.x + threadIdx.x;
    if (e >= N_EDGES) return;
    unsigned s = (unsigned)edge_src(ei, e);
    unsigned d = (unsigned)edge_dst(ei, e);
    if (s < N_NODES && d < N_NODES) atomicAdd(&g_cnt[d], 1);
}

// ---- launch 2: exclusive scan of counts -> rowptr, pos (single block, 1024 thr) ----
__global__ __launch_bounds__(1024)
void scan_kernel() {
    __shared__ int warp_sums[32];
    __shared__ int s_carry;
    const int tid = threadIdx.x, lane = tid & 31, wid = tid >> 5;
    if (tid == 0) s_carry = 0;
    __syncthreads();
    for (int base = 0; base < N_NODES; base += 1024) {
        int i = base + tid;
        int c = (i < N_NODES) ? g_cnt[i] : 0;
        int v = c;
#pragma unroll
        for (int o = 1; o < 32; o <<= 1) {
            int u = __shfl_up_sync(0xFFFFFFFFu, v, o);
            if (lane >= o) v += u;
        }
        if (lane == 31) warp_sums[wid] = v;
        __syncthreads();
        if (wid == 0) {
            int w = warp_sums[lane];
#pragma unroll
            for (int o = 1; o < 32; o <<= 1) {
                int u = __shfl_up_sync(0xFFFFFFFFu, w, o);
                if (lane >= o) w += u;
            }
            warp_sums[lane] = w;
        }
        __syncthreads();
        int warp_off = (wid == 0) ? 0 : warp_sums[wid - 1];
        int carry = s_carry;
        int excl = carry + warp_off + v - c;
        if (i < N_NODES) { g_rowptr[i] = excl; g_pos[i] = excl; }
        __syncthreads();
        if (tid == 1023) s_carry = carry + warp_sums[31];
        __syncthreads();
    }
    if (tid == 0) g_rowptr[N_NODES] = s_carry;
}

// ---- launch 3: fill CSR records {src, ew} grouped by dst ----
__global__ void fill_kernel(const int* __restrict__ ei,
                            const float* __restrict__ ew) {
    int e = blockIdx.x * blockDim.x + threadIdx.x;
    if (e >= N_EDGES) return;
    unsigned s = (unsigned)edge_src(ei, e);
    unsigned d = (unsigned)edge_dst(ei, e);
    if (s >= N_NODES || d >= N_NODES) return;
    int slot = atomicAdd(&g_pos[d], 1);
    g_rec[slot] = make_int2((int)s, __float_as_int(ew[e]));
}

// ---- launch 4: weighted in-degree from CSR -> dinv ----
__global__ void wdeg_kernel() {
    int i = blockIdx.x * blockDim.x + threadIdx.x;
    if (i >= N_NODES) return;
    int beg = g_rowptr[i], end = g_rowptr[i + 1];
    float s = 0.f;
    for (int j = beg; j < end; j++) s += __int_as_float(g_rec[j].y);
    g_dinv[i] = rsqrtf(s + 1.0f);
}

// ---- GEMM: H[N,M] = X[N,K] @ W[K,M], packed f32x2 FMAs ----
template <int K, int M, int CK>
__global__ __launch_bounds__(256)
void gemm_kernel(const float* __restrict__ X, const float* __restrict__ W,
                 float* __restrict__ H) {
    __shared__ __align__(16) float Ws[K * M];
    __shared__ __align__(16) float Xs[256 * (CK + 1)];

    const int tid = threadIdx.x;
    for (int i = tid; i < K * M; i += 256) Ws[i] = W[i];

    const int row = blockIdx.x * 256 + tid;
    ull acc[M / 2];
#pragma unroll
    for (int j = 0; j < M / 2; j++) acc[j] = 0ull;

    const int F4 = CK / 4;
    for (int kc = 0; kc < K; kc += CK) {
        __syncthreads();
        for (int idx = tid; idx < 256 * F4; idx += 256) {
            int r  = idx / F4;
            int c4 = idx % F4;
            int grow = blockIdx.x * 256 + r;
            float4 v = make_float4(0.f, 0.f, 0.f, 0.f);
            if (grow < N_NODES)
                v = *(const float4*)&X[(size_t)grow * K + kc + c4 * 4];
            float* xp = &Xs[r * (CK + 1) + c4 * 4];
            xp[0] = v.x; xp[1] = v.y; xp[2] = v.z; xp[3] = v.w;
        }
        __syncthreads();
#pragma unroll
        for (int k = 0; k < CK; k++) {
            float xv = Xs[tid * (CK + 1) + k];
            ull xx = pack2(xv, xv);
#pragma unroll
            for (int j2 = 0; j2 < M / 2; j2++) {
                ull w2 = *(const ull*)&Ws[(kc + k) * M + j2 * 2];
                acc[j2] = fma2(xx, w2, acc[j2]);
            }
        }
    }

    if (row < N_NODES) {
#pragma unroll
        for (int j4 = 0; j4 < M / 4; j4++) {
            float2 a = unpack2(acc[j4 * 2 + 0]);
            float2 b = unpack2(acc[j4 * 2 + 1]);
            *(float4*)&H[(size_t)row * M + j4 * 4] = make_float4(a.x, a.y, b.x, b.y);
        }
    }
}

// ---- fused aggregate + self-loop + bias (+relu): atomic-free CSR gather ----
template <int M, bool RELU>
__global__ __launch_bounds__(256)
void agg_kernel(const float* __restrict__ h,
                const float* __restrict__ b,
                float* __restrict__ out) {
    const int C = M / 4;
    int t = blockIdx.x * blockDim.x + threadIdx.x;
    if (t >= N_NODES * C) return;
    int node = t / C;
    int c    = t % C;
    int beg = g_rowptr[node], end = g_rowptr[node + 1];
    float dv = g_dinv[node];
    float4 acc = make_float4(0.f, 0.f, 0.f, 0.f);
    for (int j = beg; j < end; j++) {
        int2 r = __ldg(&g_rec[j]);
        float nm = g_dinv[r.x] * __int_as_float(r.y) * dv;
        float4 hv = __ldg((const float4*)&h[(size_t)r.x * M + c * 4]);
        acc.x = fmaf(nm, hv.x, acc.x);
        acc.y = fmaf(nm, hv.y, acc.y);
        acc.z = fmaf(nm, hv.z, acc.z);
        acc.w = fmaf(nm, hv.w, acc.w);
    }
    float d2 = dv * dv;
    float4 sh = *(const float4*)&h[(size_t)node * M + c * 4];
    float4 bv = *(const float4*)&b[c * 4];
    float4 o;
    o.x = fmaf(d2, sh.x, acc.x) + bv.x;
    o.y = fmaf(d2, sh.y, acc.y) + bv.y;
    o.z = fmaf(d2, sh.z, acc.z) + bv.z;
    o.w = fmaf(d2, sh.w, acc.w) + bv.w;
    if (RELU) {
        o.x = fmaxf(o.x, 0.f); o.y = fmaxf(o.y, 0.f);
        o.z = fmaxf(o.z, 0.f); o.w = fmaxf(o.w, 0.f);
    }
    *(float4*)&out[(size_t)t * 4] = o;
}

extern "C" void kernel_launch(void* const* d_in, const int* in_sizes, int n_in,
                              void* d_out, int out_size) {
    const float* x  = (const float*)d_in[0];
    const int*   ei = (const int*)d_in[1];
    const float* ew = (const float*)d_in[2];
    const float* W1 = (const float*)d_in[3];
    const float* b1 = (const float*)d_in[4];
    const float* W2 = (const float*)d_in[5];
    const float* b2 = (const float*)d_in[6];
    float* out = (float*)d_out;

    float *h1, *ag1, *h2;
    cudaGetSymbolAddress((void**)&h1,  g_h1);
    cudaGetSymbolAddress((void**)&ag1, g_ag1);
    cudaGetSymbolAddress((void**)&h2,  g_h2);

    const int T = 256;

    // CSR build (once per call; shared by both layers)
    detect_zero_kernel<<<1, 256>>>(ei);                       // 0
    count_kernel<<<(N_EDGES + T - 1) / T, T>>>(ei);           // 1
    scan_kernel<<<1, 1024>>>();                               // 2
    fill_kernel<<<(N_EDGES + T - 1) / T, T>>>(ei, ew);        // 3
    wdeg_kernel<<<(N_NODES + T - 1) / T, T>>>();              // 4

    // layer 1
    gemm_kernel<D_IN, D_HID, 16><<<(N_NODES + 255) / 256, 256>>>(x, W1, h1);   // 5
    agg_kernel<D_HID, true><<<(N_NODES * (D_HID / 4) + T - 1) / T, T>>>(h1, b1, ag1); // 6

    // layer 2
    gemm_kernel<D_HID, D_OUT, 16><<<(N_NODES + 255) / 256, 256>>>(ag1, W2, h2); // 7
    agg_kernel<D_OUT, false><<<(N_NODES * (D_OUT / 4) + T - 1) / T, T>>>(h2, b2, out); // 8
}

// round 5
// speedup vs baseline: 1.8605x; 1.3159x over previous
#include <cuda_runtime.h>

#define N_NODES 100000
#define N_EDGES 1600000
#define D_IN    128
#define D_HID   48
#define D_OUT   32
#define NB      ((N_NODES + 255) / 256)   // 391 scan blocks

typedef unsigned long long ull;

// ---- scratch (device globals: no allocation allowed) ----
__device__ __align__(16) float g_dinv[N_NODES];
__device__ __align__(16) float g_wdeg[N_NODES];
__device__ __align__(16) int   g_cnt [N_NODES];
__device__ __align__(16) int   g_rowptr[N_NODES + 1];
__device__ __align__(16) int   g_pos [N_NODES];
__device__ __align__(16) int   g_part[512];
__device__ __align__(16) int2  g_rec [N_EDGES];        // {src, norm bits} grouped by dst
__device__ __align__(16) float g_h1  [N_NODES * D_HID];
__device__ __align__(16) float g_ag1 [N_NODES * D_HID];
__device__ __align__(16) float g_h2  [N_NODES * D_OUT];
__device__ int g_is64;

__device__ __forceinline__ int edge_src(const int* ei, int e) {
    return g_is64 ? ei[2 * e] : ei[e];
}
__device__ __forceinline__ int edge_dst(const int* ei, int e) {
    return g_is64 ? ei[2 * (N_EDGES + e)] : ei[N_EDGES + e];
}

// ---- packed f32x2 FMA ----
__device__ __forceinline__ ull fma2(ull a, ull b, ull c) {
    ull d;
    asm("fma.rn.f32x2 %0, %1, %2, %3;" : "=l"(d) : "l"(a), "l"(b), "l"(c));
    return d;
}
__device__ __forceinline__ ull pack2(float lo, float hi) {
    ull d;
    asm("mov.b64 %0, {%1, %2};" : "=l"(d) : "r"(__float_as_uint(lo)), "r"(__float_as_uint(hi)));
    return d;
}
__device__ __forceinline__ float2 unpack2(ull v) {
    unsigned lo, hi;
    asm("mov.b64 {%0, %1}, %2;" : "=r"(lo), "=r"(hi) : "l"(v));
    return make_float2(__uint_as_float(lo), __uint_as_float(hi));
}

// ---- zero counters (gridded) ----
__global__ void zero_kernel() {
    int i = blockIdx.x * blockDim.x + threadIdx.x;
    if (i < N_NODES) { g_cnt[i] = 0; g_wdeg[i] = 0.f; }
}

// ---- dtype detect (1 block) ----
__global__ void detect_kernel(const int* __restrict__ ei32) {
    __shared__ int acc;
    if (threadIdx.x == 0) acc = 0;
    __syncthreads();
    int v = 0;
    for (int i = threadIdx.x; i < 2048; i += 256) v |= ei32[2 * i + 1];
    atomicOr(&acc, v);
    __syncthreads();
    if (threadIdx.x == 0) g_is64 = (acc == 0) ? 1 : 0;
}

// ---- count + weighted degree ----
__global__ void count_kernel(const int* __restrict__ ei,
                             const float* __restrict__ ew) {
    int e = blockIdx.x * blockDim.x + threadIdx.x;
    if (e >= N_EDGES) return;
    unsigned s = (unsigned)edge_src(ei, e);
    unsigned d = (unsigned)edge_dst(ei, e);
    if (s < N_NODES && d < N_NODES) {
        atomicAdd(&g_cnt[d], 1);
        atomicAdd(&g_wdeg[d], ew[e]);
    }
}

// ---- scan phase 1: per-block sums of cnt ----
__global__ __launch_bounds__(256)
void scan1_kernel() {
    __shared__ int ws[8];
    int t = threadIdx.x, lane = t & 31, wid = t >> 5;
    int i = blockIdx.x * 256 + t;
    int v = (i < N_NODES) ? g_cnt[i] : 0;
#pragma unroll
    for (int o = 16; o > 0; o >>= 1) v += __shfl_down_sync(0xFFFFFFFFu, v, o);
    if (lane == 0) ws[wid] = v;
    __syncthreads();
    if (t == 0) {
        int s = 0;
#pragma unroll
        for (int w = 0; w < 8; w++) s += ws[w];
        g_part[blockIdx.x] = s;
    }
}

// ---- scan phase 2: exclusive scan of 391 block sums (1 block, 512 thr) ----
__global__ __launch_bounds__(512)
void scan2_kernel() {
    __shared__ int ws[16];
    int t = threadIdx.x, lane = t & 31, wid = t >> 5;
    int orig = (t < NB) ? g_part[t] : 0;
    int v = orig;
#pragma unroll
    for (int o = 1; o < 32; o <<= 1) {
        int u = __shfl_up_sync(0xFFFFFFFFu, v, o);
        if (lane >= o) v += u;
    }
    if (lane == 31) ws[wid] = v;
    __syncthreads();
    if (wid == 0) {
        int w = (lane < 16) ? ws[lane] : 0;
#pragma unroll
        for (int o = 1; o < 16; o <<= 1) {
            int u = __shfl_up_sync(0xFFFFFFFFu, w, o);
            if (lane >= o) w += u;
        }
        if (lane < 16) ws[lane] = w;
    }
    __syncthreads();
    int off = (wid == 0) ? 0 : ws[wid - 1];
    int incl = off + v;
    if (t < NB) g_part[t] = incl - orig;
    if (t == NB - 1) g_rowptr[N_NODES] = incl;
}

// ---- scan phase 3: local exclusive rescan + offset; also dinv ----
__global__ __launch_bounds__(256)
void scan3_kernel() {
    __shared__ int ws[8];
    int t = threadIdx.x, lane = t & 31, wid = t >> 5;
    int i = blockIdx.x * 256 + t;
    int c = (i < N_NODES) ? g_cnt[i] : 0;
    int v = c;
#pragma unroll
    for (int o = 1; o < 32; o <<= 1) {
        int u = __shfl_up_sync(0xFFFFFFFFu, v, o);
        if (lane >= o) v += u;
    }
    if (lane == 31) ws[wid] = v;
    __syncthreads();
    if (wid == 0) {
        int w = (lane < 8) ? ws[lane] : 0;
#pragma unroll
        for (int o = 1; o < 8; o <<= 1) {
            int u = __shfl_up_sync(0xFFFFFFFFu, w, o);
            if (lane >= o) w += u;
        }
        if (lane < 8) ws[lane] = w;
    }
    __syncthreads();
    int woff = (wid == 0) ? 0 : ws[wid - 1];
    int excl = g_part[blockIdx.x] + woff + v - c;
    if (i < N_NODES) {
        g_rowptr[i] = excl;
        g_pos[i]    = excl;
        g_dinv[i]   = rsqrtf(g_wdeg[i] + 1.0f);
    }
}

// ---- fill CSR records {src, premultiplied norm} ----
__global__ void fill_kernel(const int* __restrict__ ei,
                            const float* __restrict__ ew) {
    int e = blockIdx.x * blockDim.x + threadIdx.x;
    if (e >= N_EDGES) return;
    unsigned s = (unsigned)edge_src(ei, e);
    unsigned d = (unsigned)edge_dst(ei, e);
    if (s >= N_NODES || d >= N_NODES) return;
    int slot = atomicAdd(&g_pos[d], 1);
    float nm = g_dinv[s] * ew[e] * g_dinv[d];
    g_rec[slot] = make_int2((int)s, __float_as_int(nm));
}

// ---- GEMM: H[N,M] = X[N,K] @ W[K,M], packed f32x2 FMAs ----
template <int K, int M, int CK>
__global__ __launch_bounds__(256)
void gemm_kernel(const float* __restrict__ X, const float* __restrict__ W,
                 float* __restrict__ H) {
    __shared__ __align__(16) float Ws[K * M];
    __shared__ __align__(16) float Xs[256 * (CK + 1)];

    const int tid = threadIdx.x;
    for (int i = tid; i < K * M; i += 256) Ws[i] = W[i];

    const int row = blockIdx.x * 256 + tid;
    ull acc[M / 2];
#pragma unroll
    for (int j = 0; j < M / 2; j++) acc[j] = 0ull;

    const int F4 = CK / 4;
    for (int kc = 0; kc < K; kc += CK) {
        __syncthreads();
        for (int idx = tid; idx < 256 * F4; idx += 256) {
            int r  = idx / F4;
            int c4 = idx % F4;
            int grow = blockIdx.x * 256 + r;
            float4 v = make_float4(0.f, 0.f, 0.f, 0.f);
            if (grow < N_NODES)
                v = *(const float4*)&X[(size_t)grow * K + kc + c4 * 4];
            float* xp = &Xs[r * (CK + 1) + c4 * 4];
            xp[0] = v.x; xp[1] = v.y; xp[2] = v.z; xp[3] = v.w;
        }
        __syncthreads();
#pragma unroll
        for (int k = 0; k < CK; k++) {
            float xv = Xs[tid * (CK + 1) + k];
            ull xx = pack2(xv, xv);
#pragma unroll
            for (int j2 = 0; j2 < M / 2; j2++) {
                ull w2 = *(const ull*)&Ws[(kc + k) * M + j2 * 2];
                acc[j2] = fma2(xx, w2, acc[j2]);
            }
        }
    }

    if (row < N_NODES) {
#pragma unroll
        for (int j4 = 0; j4 < M / 4; j4++) {
            float2 a = unpack2(acc[j4 * 2 + 0]);
            float2 b = unpack2(acc[j4 * 2 + 1]);
            *(float4*)&H[(size_t)row * M + j4 * 4] = make_float4(a.x, a.y, b.x, b.y);
        }
    }
}

// ---- fused aggregate + self-loop + bias (+relu), 2x unrolled ----
template <int M, bool RELU>
__global__ __launch_bounds__(256)
void agg_kernel(const float* __restrict__ h,
                const float* __restrict__ b,
                float* __restrict__ out) {
    const int C = M / 4;
    int t = blockIdx.x * blockDim.x + threadIdx.x;
    if (t >= N_NODES * C) return;
    int node = t / C;
    int c    = t % C;
    int beg = __ldg(&g_rowptr[node]);
    int end = __ldg(&g_rowptr[node + 1]);
    float4 acc = make_float4(0.f, 0.f, 0.f, 0.f);
    int j = beg;
    for (; j + 2 <= end; j += 2) {
        int2 r0 = __ldg(&g_rec[j]);
        int2 r1 = __ldg(&g_rec[j + 1]);
        float4 h0 = __ldg((const float4*)&h[(size_t)r0.x * M + c * 4]);
        float4 h1 = __ldg((const float4*)&h[(size_t)r1.x * M + c * 4]);
        float n0 = __int_as_float(r0.y);
        float n1 = __int_as_float(r1.y);
        acc.x = fmaf(n0, h0.x, acc.x); acc.y = fmaf(n0, h0.y, acc.y);
        acc.z = fmaf(n0, h0.z, acc.z); acc.w = fmaf(n0, h0.w, acc.w);
        acc.x = fmaf(n1, h1.x, acc.x); acc.y = fmaf(n1, h1.y, acc.y);
        acc.z = fmaf(n1, h1.z, acc.z); acc.w = fmaf(n1, h1.w, acc.w);
    }
    if (j < end) {
        int2 r0 = __ldg(&g_rec[j]);
        float4 h0 = __ldg((const float4*)&h[(size_t)r0.x * M + c * 4]);
        float n0 = __int_as_float(r0.y);
        acc.x = fmaf(n0, h0.x, acc.x); acc.y = fmaf(n0, h0.y, acc.y);
        acc.z = fmaf(n0, h0.z, acc.z); acc.w = fmaf(n0, h0.w, acc.w);
    }
    float dv = g_dinv[node];
    float d2 = dv * dv;
    float4 sh = *(const float4*)&h[(size_t)node * M + c * 4];
    float4 bv = *(const float4*)&b[c * 4];
    float4 o;
    o.x = fmaf(d2, sh.x, acc.x) + bv.x;
    o.y = fmaf(d2, sh.y, acc.y) + bv.y;
    o.z = fmaf(d2, sh.z, acc.z) + bv.z;
    o.w = fmaf(d2, sh.w, acc.w) + bv.w;
    if (RELU) {
        o.x = fmaxf(o.x, 0.f); o.y = fmaxf(o.y, 0.f);
        o.z = fmaxf(o.z, 0.f); o.w = fmaxf(o.w, 0.f);
    }
    *(float4*)&out[(size_t)t * 4] = o;
}

extern "C" void kernel_launch(void* const* d_in, const int* in_sizes, int n_in,
                              void* d_out, int out_size) {
    const float* x  = (const float*)d_in[0];
    const int*   ei = (const int*)d_in[1];
    const float* ew = (const float*)d_in[2];
    const float* W1 = (const float*)d_in[3];
    const float* b1 = (const float*)d_in[4];
    const float* W2 = (const float*)d_in[5];
    const float* b2 = (const float*)d_in[6];
    float* out = (float*)d_out;

    float *h1, *ag1, *h2;
    cudaGetSymbolAddress((void**)&h1,  g_h1);
    cudaGetSymbolAddress((void**)&ag1, g_ag1);
    cudaGetSymbolAddress((void**)&h2,  g_h2);

    const int T = 256;
    const int EB = (N_EDGES + T - 1) / T;

    // CSR build
    zero_kernel<<<NB, T>>>();
    detect_kernel<<<1, 256>>>(ei);
    count_kernel<<<EB, T>>>(ei, ew);
    scan1_kernel<<<NB, T>>>();
    scan2_kernel<<<1, 512>>>();
    scan3_kernel<<<NB, T>>>();
    fill_kernel<<<EB, T>>>(ei, ew);

    // layer 1
    gemm_kernel<D_IN, D_HID, 16><<<NB, 256>>>(x, W1, h1);
    agg_kernel<D_HID, true><<<(N_NODES * (D_HID / 4) + T - 1) / T, T>>>(h1, b1, ag1);

    // layer 2
    gemm_kernel<D_HID, D_OUT, 16><<<NB, 256>>>(ag1, W2, h2);
    agg_kernel<D_OUT, false><<<(N_NODES * (D_OUT / 4) + T - 1) / T, T>>>(h2, b2, out);
}